// round 10
// baseline (speedup 1.0000x reference)
#include <cuda_runtime.h>
#include <cstdint>

#define N 2304
#define BB 1024
#define FF 32
#define TEAM 72
#define NCTA (2 * TEAM)
#define NTHR 1024
#define PF 1152                     // prefetched cols (fwd) / rows (bwd), half slab
#define SW_FLOATS (32 * PF)         // 36864 floats = 144 KB
#define SMEM_BYTES ((SW_FLOATS + N + 1024) * 4)   // 160768

// device scratch (no allocation allowed)
__device__ float g_v[FF * N];
__device__ float g_z[FF * N];
__device__ float g_keep[FF * N];
__device__ float g_vsum[TEAM];
__device__ int   g_cntF[64];
__device__ int   g_cntB[64];
__device__ int   g_cntAll;

__global__ void init_kernel() {
    int i = blockIdx.x * blockDim.x + threadIdx.x;
    if (i < FF * N) g_keep[i] = 1.0f;
    if (i < 64) { g_cntF[i] = 0; g_cntB[i] = 0; }
    if (i == 64) g_cntAll = 0;
}

__global__ void scatter_kernel(const int* __restrict__ sel) {
    int i = threadIdx.x;
    if (i < 256) {
        int f = sel[3 * i];
        int node = sel[3 * i + 1] * 64 + sel[3 * i + 2];
        g_keep[f * N + node] = 0.0f;
    }
}

__device__ __forceinline__ void teambar(int* cnt, int s) {
    __threadfence();
    __syncthreads();
    if (threadIdx.x == 0) {
        atomicAdd(&cnt[s], 1);
        volatile int* c = &cnt[s];
        while (*c < TEAM) { }
        __threadfence();
    }
    __syncthreads();
}

__device__ __forceinline__ void cpasync16(uint32_t dst, const void* src) {
    asm volatile("cp.async.cg.shared.global [%0], [%1], 16;" :: "r"(dst), "l"(src));
}

// Persistent solver + fused final combine.
// CTAs 0..71:   forward chain  v_f = keep_f * (b_f + W[f-1] @ v_{f-1})
// CTAs 72..143: backward chain z_f = 1 + W[f]^T @ (keep_{f+1} * z_{f+1})
// Half of the next step's weight slab is cp.async-prefetched into smem during
// the barrier/staging dead time (weights are barrier-independent).
__global__ void __launch_bounds__(NTHR, 1)
solve_kernel(const float* __restrict__ W, const float* __restrict__ B,
             const int* __restrict__ cand, float* __restrict__ out)
{
    extern __shared__ float smem[];
    float* s_w  = smem;                 // [32][PF] fwd  /  [PF][32] bwd
    float* s_v  = smem + SW_FLOATS;     // [N]
    float* s_red = s_v + N;             // [1024]

    uint32_t swb;
    asm("{ .reg .u64 t; cvta.to.shared.u64 t, %1; cvt.u32.u64 %0, t; }" : "=r"(swb) : "l"(s_w));

    int tid = threadIdx.x;
    int cta = blockIdx.x;
    int warp = tid >> 5, lane = tid & 31;

    if (cta < TEAM) {
        // ================= FORWARD TEAM =================
        int r0 = cta * 32;
        float myacc = 0.f;

        auto pf_issue = [&](int f) {    // prefetch W[f-1] rows r0..r0+31, cols 0..PF
            const float* base = W + (size_t)(f - 1) * N * N;
            #pragma unroll
            for (int k = 0; k < 9; ++k) {
                int c = tid + k * 1024;          // 9216 chunks
                int row = c / 288;               // PF/4 = 288 float4 per row
                int col4 = c - row * 288;
                cpasync16(swb + (uint32_t)(row * (PF * 4) + col4 * 16),
                          (const float4*)(base + (size_t)(r0 + row) * N) + col4);
            }
            asm volatile("cp.async.commit_group;");
        };

        if (tid < 32) {
            int row = r0 + tid;
            float v = g_keep[row] * B[row];
            g_v[row] = v;
            myacc += v;
        }
        pf_issue(1);
        teambar(g_cntF, 0);

        for (int f = 1; f < FF; ++f) {
            for (int n = tid; n < N; n += NTHR) s_v[n] = g_v[(f - 1) * N + n];
            asm volatile("cp.async.wait_group 0;" ::: "memory");
            __syncthreads();

            int ra = r0 + warp;                  // 32 warps x 1 row
            const float4* ws = (const float4*)(s_w + warp * PF);
            const float4* wg = (const float4*)(W + ((size_t)(f - 1) * N + ra) * N);
            const float4* v4 = (const float4*)s_v;
            float acc0 = 0.f;
            #pragma unroll
            for (int i = 0; i < 9; ++i) {        // smem half: cols 0..1151
                int idx = lane + i * 32;
                float4 vv = v4[idx];
                float4 a4 = ws[idx];
                acc0 += a4.x * vv.x + a4.y * vv.y + a4.z * vv.z + a4.w * vv.w;
            }
            #pragma unroll
            for (int i = 9; i < 18; ++i) {       // gmem half: cols 1152..2303
                int idx = lane + i * 32;
                float4 vv = v4[idx];
                float4 a4 = wg[idx];
                acc0 += a4.x * vv.x + a4.y * vv.y + a4.z * vv.z + a4.w * vv.w;
            }
            #pragma unroll
            for (int o = 16; o; o >>= 1)
                acc0 += __shfl_xor_sync(0xffffffffu, acc0, o);
            if (lane == 0) {
                float va = g_keep[f * N + ra] * (B[f * N + ra] + acc0);
                g_v[f * N + ra] = va;
                myacc += va;
            }
            __syncthreads();                     // all warps done with s_w
            if (f < FF - 1) {
                pf_issue(f + 1);                 // overlaps the barrier spin
                teambar(g_cntF, f);
            }
        }

        #pragma unroll
        for (int o = 16; o; o >>= 1) myacc += __shfl_xor_sync(0xffffffffu, myacc, o);
        if (lane == 0) s_red[warp] = myacc;
        __syncthreads();
        if (tid == 0) {
            float t = 0.f;
            #pragma unroll
            for (int w = 0; w < 32; ++w) t += s_red[w];
            g_vsum[cta] = t;
        }
    } else {
        // ================= BACKWARD TEAM =================
        int id = cta - TEAM;
        int c0 = id * 32;

        auto pf_issue = [&](int f) {    // prefetch W[f] rows 0..PF, cols c0..c0+31
            const float* base = W + (size_t)f * N * N + c0;
            #pragma unroll
            for (int k = 0; k < 9; ++k) {
                int c = tid + k * 1024;          // 9216 chunks
                int row = c >> 3;                // 8 x 16B per row
                int part = c & 7;
                cpasync16(swb + (uint32_t)(row * 128 + part * 16),
                          (const float4*)(base + (size_t)row * N) + part);
            }
            asm volatile("cp.async.commit_group;");
        };

        if (tid < 32) g_z[31 * N + c0 + tid] = 1.0f;
        pf_issue(30);
        teambar(g_cntB, 0);

        for (int f = FF - 2; f >= 0; --f) {
            for (int n = tid; n < N; n += NTHR)
                s_v[n] = g_keep[(f + 1) * N + n] * g_z[(f + 1) * N + n];
            asm volatile("cp.async.wait_group 0;" ::: "memory");
            __syncthreads();

            int tx = tid & 31, ty = tid >> 5;    // 32 cols x 32 row-lanes
            const float* wp = W + (size_t)f * N * N + c0 + tx;
            float a0 = 0.f, a1 = 0.f, a2 = 0.f, a3 = 0.f;
            #pragma unroll 4
            for (int i = 0; i < 36; i += 4) {    // smem half: rows 0..1151
                int n0 = ty + (i + 0) * 32;
                int n1 = ty + (i + 1) * 32;
                int n2 = ty + (i + 2) * 32;
                int n3 = ty + (i + 3) * 32;
                a0 += s_w[n0 * 32 + tx] * s_v[n0];
                a1 += s_w[n1 * 32 + tx] * s_v[n1];
                a2 += s_w[n2 * 32 + tx] * s_v[n2];
                a3 += s_w[n3 * 32 + tx] * s_v[n3];
            }
            #pragma unroll 4
            for (int i = 36; i < 72; i += 4) {   // gmem half: rows 1152..2303
                int n0 = ty + (i + 0) * 32;
                int n1 = ty + (i + 1) * 32;
                int n2 = ty + (i + 2) * 32;
                int n3 = ty + (i + 3) * 32;
                a0 += wp[(size_t)n0 * N] * s_v[n0];
                a1 += wp[(size_t)n1 * N] * s_v[n1];
                a2 += wp[(size_t)n2 * N] * s_v[n2];
                a3 += wp[(size_t)n3 * N] * s_v[n3];
            }
            s_red[tid] = (a0 + a1) + (a2 + a3);
            __syncthreads();
            #pragma unroll
            for (int s2 = 512; s2 >= 32; s2 >>= 1) {
                if (tid < s2) s_red[tid] += s_red[tid + s2];
                __syncthreads();
            }
            if (tid < 32) g_z[f * N + c0 + tid] = 1.0f + s_red[tid];
            if (f > 0) {
                pf_issue(f - 1);                 // overlaps the barrier spin
                teambar(g_cntB, 31 - f);
            }
        }
    }

    // ================= FUSED FINAL =================
    __threadfence();
    __syncthreads();
    if (tid == 0) atomicAdd(&g_cntAll, 1);
    if (cta == 0) {
        if (tid == 0) {
            volatile int* c = &g_cntAll;
            while (*c < NCTA) { }
            __threadfence();
        }
        __syncthreads();
        float t = (tid < TEAM) ? g_vsum[tid] : 0.f;
        if (tid < 128) {
            #pragma unroll
            for (int o = 16; o; o >>= 1) t += __shfl_xor_sync(0xffffffffu, t, o);
            if ((tid & 31) == 0) s_red[tid >> 5] = t;
        }
        __syncthreads();
        if (tid == 0) s_red[0] = s_red[0] + s_red[1] + s_red[2] + s_red[3];
        __syncthreads();
        float TOT = s_red[0];
        int cf = cand[3 * tid];
        int cn = cand[3 * tid + 1] * 64 + cand[3 * tid + 2];
        out[tid] = TOT - g_v[cf * N + cn] * g_z[cf * N + cn];
    }
}

extern "C" void kernel_launch(void* const* d_in, const int* in_sizes, int n_in,
                              void* d_out, int out_size) {
    const float* weights = (const float*)d_in[0];
    const float* biases  = (const float*)d_in[1];
    const int*   sel     = (const int*)d_in[2];
    const int*   cand    = (const int*)d_in[3];
    float*       out     = (float*)d_out;

    cudaFuncSetAttribute(solve_kernel, cudaFuncAttributeMaxDynamicSharedMemorySize, SMEM_BYTES);

    init_kernel<<<(FF * N + 255) / 256, 256>>>();
    scatter_kernel<<<1, 256>>>(sel);
    solve_kernel<<<NCTA, NTHR, SMEM_BYTES>>>(weights, biases, cand, out);
}

// round 11
// speedup vs baseline: 1.1478x; 1.1478x over previous
#include <cuda_runtime.h>
#include <cstdint>

#define N 2304
#define BB 1024
#define FF 32
#define TEAM 72
#define NCTA (2 * TEAM)
#define NTHR 1024

// device scratch (no allocation allowed)
__device__ float g_v[FF * N];       // forward shared state per frame
__device__ float g_z[FF * N];       // backward adjoint per frame
__device__ float g_keep[FF * N];    // keep mask
__device__ float g_vsum[TEAM];      // per-forward-CTA partial of sum_f sum(v_f)
__device__ int   g_cntF[64];        // forward-team barrier counters
__device__ int   g_cntB[64];        // backward-team barrier counters
__device__ int   g_cntAll;          // all-CTA completion counter

// one launch: keep-mask init + scatter + counter reset (single CTA)
__global__ void setup_kernel(const int* __restrict__ sel) {
    int tid = threadIdx.x;
    for (int i = tid; i < FF * N; i += NTHR) g_keep[i] = 1.0f;
    if (tid < 64) { g_cntF[tid] = 0; g_cntB[tid] = 0; }
    if (tid == 64) g_cntAll = 0;
    __syncthreads();
    if (tid < 256) {
        int f = sel[3 * tid];
        int node = sel[3 * tid + 1] * 64 + sel[3 * tid + 2];
        g_keep[f * N + node] = 0.0f;
    }
}

__device__ __forceinline__ void teambar(int* cnt, int s) {
    __threadfence();
    __syncthreads();
    if (threadIdx.x == 0) {
        atomicAdd(&cnt[s], 1);
        volatile int* c = &cnt[s];
        while (*c < TEAM) { }
        __threadfence();
    }
    __syncthreads();
}

// Persistent solver + fused final combine.
// CTAs 0..71:   forward chain  v_f = keep_f * (b_f + W[f-1] @ v_{f-1})
// CTAs 72..143: backward chain z_f = 1 + W[f]^T @ (keep_{f+1} * z_{f+1})
__global__ void __launch_bounds__(NTHR, 1)
solve_kernel(const float* __restrict__ W, const float* __restrict__ B,
             const int* __restrict__ cand, float* __restrict__ out)
{
    __shared__ float s_v[N];
    __shared__ float s_red[32 * 33];      // padded transpose for backward reduce

    int tid = threadIdx.x;
    int cta = blockIdx.x;
    int warp = tid >> 5, lane = tid & 31;

    if (cta < TEAM) {
        // ================= FORWARD TEAM =================
        int r0 = cta * 32;                       // 32 rows per CTA
        float myacc = 0.f;

        if (tid < 32) {
            int row = r0 + tid;
            float v = g_keep[row] * B[row];
            g_v[row] = v;
            myacc += v;
        }
        teambar(g_cntF, 0);

        for (int f = 1; f < FF; ++f) {
            for (int n = tid; n < N; n += NTHR) s_v[n] = g_v[(f - 1) * N + n];
            __syncthreads();

            int ra = r0 + warp;                  // 32 warps x 1 row
            const float4* wa = (const float4*)(W + ((size_t)(f - 1) * N + ra) * N);
            const float4* v4 = (const float4*)s_v;
            float acc0 = 0.f;
            #pragma unroll
            for (int i = 0; i < 18; ++i) {       // 576 float4 / 32 lanes
                int idx = lane + i * 32;
                float4 vv = v4[idx];
                float4 a4 = wa[idx];
                acc0 += a4.x * vv.x + a4.y * vv.y + a4.z * vv.z + a4.w * vv.w;
            }
            #pragma unroll
            for (int o = 16; o; o >>= 1)
                acc0 += __shfl_xor_sync(0xffffffffu, acc0, o);
            if (lane == 0) {
                float va = g_keep[f * N + ra] * (B[f * N + ra] + acc0);
                g_v[f * N + ra] = va;
                myacc += va;
            }
            if (f < FF - 1) teambar(g_cntF, f);
        }

        // block-reduce myacc (fixed tree -> deterministic)
        #pragma unroll
        for (int o = 16; o; o >>= 1) myacc += __shfl_xor_sync(0xffffffffu, myacc, o);
        if (lane == 0) s_red[warp] = myacc;
        __syncthreads();
        if (tid == 0) {
            float t = 0.f;
            #pragma unroll
            for (int w = 0; w < 32; ++w) t += s_red[w];
            g_vsum[cta] = t;
        }
    } else {
        // ================= BACKWARD TEAM =================
        int id = cta - TEAM;
        int c0 = id * 32;                        // 32 cols per CTA

        if (tid < 32) g_z[31 * N + c0 + tid] = 1.0f;
        teambar(g_cntB, 0);

        for (int f = FF - 2; f >= 0; --f) {
            for (int n = tid; n < N; n += NTHR)
                s_v[n] = g_keep[(f + 1) * N + n] * g_z[(f + 1) * N + n];
            __syncthreads();

            int tx = lane, ty = warp;            // 32 cols x 32 row-lanes
            const float* wp = W + (size_t)f * N * N + c0 + tx;
            float a0 = 0.f, a1 = 0.f, a2 = 0.f, a3 = 0.f;
            float a4 = 0.f, a5 = 0.f, a6 = 0.f, a7 = 0.f;
            #pragma unroll
            for (int i = 0; i < 72; i += 8) {    // n = ty + 32*i
                int n0 = ty + (i + 0) * 32;
                int n1 = ty + (i + 1) * 32;
                int n2 = ty + (i + 2) * 32;
                int n3 = ty + (i + 3) * 32;
                int n4 = ty + (i + 4) * 32;
                int n5 = ty + (i + 5) * 32;
                int n6 = ty + (i + 6) * 32;
                int n7 = ty + (i + 7) * 32;
                a0 += wp[(size_t)n0 * N] * s_v[n0];
                a1 += wp[(size_t)n1 * N] * s_v[n1];
                a2 += wp[(size_t)n2 * N] * s_v[n2];
                a3 += wp[(size_t)n3 * N] * s_v[n3];
                a4 += wp[(size_t)n4 * N] * s_v[n4];
                a5 += wp[(size_t)n5 * N] * s_v[n5];
                a6 += wp[(size_t)n6 * N] * s_v[n6];
                a7 += wp[(size_t)n7 * N] * s_v[n7];
            }
            float p = ((a0 + a1) + (a2 + a3)) + ((a4 + a5) + (a6 + a7));

            // transpose into padded smem, one sync, warp-shuffle reduce
            s_red[tx * 33 + ty] = p;
            __syncthreads();
            float q = s_red[warp * 33 + lane];   // warp w gathers col c0+w partials
            #pragma unroll
            for (int o = 16; o; o >>= 1)
                q += __shfl_xor_sync(0xffffffffu, q, o);
            if (lane == 0) g_z[f * N + c0 + warp] = 1.0f + q;
            __syncthreads();                     // s_red reuse safety next iter
            if (f > 0) teambar(g_cntB, 31 - f);
        }
    }

    // ================= FUSED FINAL =================
    __threadfence();
    __syncthreads();
    if (tid == 0) atomicAdd(&g_cntAll, 1);
    if (cta == 0) {
        if (tid == 0) {
            volatile int* c = &g_cntAll;
            while (*c < NCTA) { }
            __threadfence();
        }
        __syncthreads();
        float t = (tid < TEAM) ? g_vsum[tid] : 0.f;
        if (tid < 128) {
            #pragma unroll
            for (int o = 16; o; o >>= 1) t += __shfl_xor_sync(0xffffffffu, t, o);
            if ((tid & 31) == 0) s_red[tid >> 5] = t;
        }
        __syncthreads();
        if (tid == 0) s_red[0] = s_red[0] + s_red[1] + s_red[2] + s_red[3];
        __syncthreads();
        float TOT = s_red[0];
        int cf = cand[3 * tid];
        int cn = cand[3 * tid + 1] * 64 + cand[3 * tid + 2];
        out[tid] = TOT - g_v[cf * N + cn] * g_z[cf * N + cn];
    }
}

extern "C" void kernel_launch(void* const* d_in, const int* in_sizes, int n_in,
                              void* d_out, int out_size) {
    const float* weights = (const float*)d_in[0];
    const float* biases  = (const float*)d_in[1];
    const int*   sel     = (const int*)d_in[2];
    const int*   cand    = (const int*)d_in[3];
    float*       out     = (float*)d_out;

    setup_kernel<<<1, NTHR>>>(sel);
    solve_kernel<<<NCTA, NTHR>>>(weights, biases, cand, out);
}

// round 12
// speedup vs baseline: 1.2610x; 1.0986x over previous
#include <cuda_runtime.h>
#include <cstdint>

#define N 2304
#define BB 1024
#define FF 32
#define TEAM 72
#define NCTA (2 * TEAM)
#define NTHR 1024

#define CPS 9                      // chunks per step
#define CW 256                     // chunk extent along the streamed dim
#define SLOT_FLOATS (32 * CW)      // 8192 floats = 32 KB
#define RING 5                     // smem ring slots
#define DEPTH 4                    // chunks in flight
#define TOTAL (31 * CPS)           // 279 chunks per team member
#define SMEM_BYTES ((RING * SLOT_FLOATS + N + 32 * 33) * 4)   // 177280

// device scratch (no allocation allowed)
__device__ float g_v[FF * N];
__device__ float g_z[FF * N];
__device__ float g_keep[FF * N];
__device__ float g_vsum[TEAM];
__device__ int   g_cntF[64];
__device__ int   g_cntB[64];
__device__ int   g_cntAll;

__global__ void setup_kernel(const int* __restrict__ sel) {
    int tid = threadIdx.x;
    for (int i = tid; i < FF * N; i += NTHR) g_keep[i] = 1.0f;
    if (tid < 64) { g_cntF[tid] = 0; g_cntB[tid] = 0; }
    if (tid == 64) g_cntAll = 0;
    __syncthreads();
    if (tid < 256) {
        int f = sel[3 * tid];
        int node = sel[3 * tid + 1] * 64 + sel[3 * tid + 2];
        g_keep[f * N + node] = 0.0f;
    }
}

__device__ __forceinline__ void teambar(int* cnt, int s) {
    __threadfence();
    __syncthreads();
    if (threadIdx.x == 0) {
        atomicAdd(&cnt[s], 1);
        volatile int* c = &cnt[s];
        while (*c < TEAM) { }
        __threadfence();
    }
    __syncthreads();
}

__device__ __forceinline__ void cpasync16(uint32_t dst, const void* src) {
    asm volatile("cp.async.cg.shared.global [%0], [%1], 16;" :: "r"(dst), "l"(src));
}
__device__ __forceinline__ void cpcommit() {
    asm volatile("cp.async.commit_group;");
}
__device__ __forceinline__ void cpwait3() {
    asm volatile("cp.async.wait_group 3;" ::: "memory");
}
__device__ __forceinline__ void cpwait0() {
    asm volatile("cp.async.wait_group 0;" ::: "memory");
}

// Persistent solver + fused final combine.
// CTAs 0..71:   forward  v_f = keep_f * (b_f + W[f-1] @ v_{f-1})   (32 rows each)
// CTAs 72..143: backward z_f = 1 + W[f]^T @ (keep_{f+1} * z_{f+1}) (32 cols each)
// Weights stream via a cp.async chunk pipeline that runs CONTINUOUSLY across
// step boundaries (chunk addresses are vector-independent), keeping DRAM busy
// through the team barrier and vector staging.
__global__ void __launch_bounds__(NTHR, 1)
solve_kernel(const float* __restrict__ W, const float* __restrict__ B,
             const int* __restrict__ cand, float* __restrict__ out)
{
    extern __shared__ float smem[];
    float* s_slot = smem;                      // RING x 8192 floats
    float* s_v    = smem + RING * SLOT_FLOATS; // N
    float* s_red  = s_v + N;                   // 32x33

    uint32_t sbase;
    asm("{ .reg .u64 t; cvta.to.shared.u64 t, %1; cvt.u32.u64 %0, t; }" : "=r"(sbase) : "l"(smem));

    int tid = threadIdx.x;
    int cta = blockIdx.x;
    int warp = tid >> 5, lane = tid & 31;

    if (cta < TEAM) {
        // ================= FORWARD TEAM =================
        int r0 = cta * 32;
        float myacc = 0.f;

        // chunk idx -> slab ff = idx/9 (W[ff] used by step f=ff+1), col block cc
        auto issue = [&](int idx) {
            int ff = idx / CPS, cc = idx - ff * CPS;
            const float* base = W + ((size_t)ff * N + r0) * N + cc * CW;
            uint32_t dst = sbase + (uint32_t)(idx % RING) * (SLOT_FLOATS * 4);
            #pragma unroll
            for (int k = 0; k < 2; ++k) {
                int e = tid + k * 1024;          // e = row*64 + q  (row<32, q<64)
                int row = e >> 6, q = e & 63;
                cpasync16(dst + (uint32_t)e * 16, base + (size_t)row * N + q * 4);
            }
            cpcommit();
        };

        int issued = 0;
        #pragma unroll
        for (int i = 0; i < DEPTH; ++i) issue(issued++);

        if (tid < 32) {
            int row = r0 + tid;
            float v = g_keep[row] * B[row];
            g_v[row] = v;
            myacc += v;
        }
        teambar(g_cntF, 0);

        for (int f = 1; f < FF; ++f) {
            for (int n = tid; n < N; n += NTHR) s_v[n] = g_v[(f - 1) * N + n];

            float acc = 0.f;
            int g0 = (f - 1) * CPS;
            #pragma unroll
            for (int c = 0; c < CPS; ++c) {
                if (issued < TOTAL) cpwait3(); else cpwait0();
                __syncthreads();                 // chunk g0+c visible; slot reuse safe
                if (issued < TOTAL) issue(issued++);

                const float4* wrow = (const float4*)(s_slot + ((g0 + c) % RING) * SLOT_FLOATS + warp * CW);
                const float4* vv   = (const float4*)(s_v + c * CW);
                float4 w0 = wrow[lane],      v0 = vv[lane];
                float4 w1 = wrow[lane + 32], v1 = vv[lane + 32];
                acc += w0.x * v0.x + w0.y * v0.y + w0.z * v0.z + w0.w * v0.w;
                acc += w1.x * v1.x + w1.y * v1.y + w1.z * v1.z + w1.w * v1.w;
            }
            #pragma unroll
            for (int o = 16; o; o >>= 1)
                acc += __shfl_xor_sync(0xffffffffu, acc, o);
            int ra = r0 + warp;
            if (lane == 0) {
                float va = g_keep[f * N + ra] * (B[f * N + ra] + acc);
                g_v[f * N + ra] = va;
                myacc += va;
            }
            if (f < FF - 1) teambar(g_cntF, f);
        }

        #pragma unroll
        for (int o = 16; o; o >>= 1) myacc += __shfl_xor_sync(0xffffffffu, myacc, o);
        if (lane == 0) s_red[warp] = myacc;
        __syncthreads();
        if (tid == 0) {
            float t = 0.f;
            #pragma unroll
            for (int w = 0; w < 32; ++w) t += s_red[w];
            g_vsum[cta] = t;
        }
    } else {
        // ================= BACKWARD TEAM =================
        int id = cta - TEAM;
        int c0 = id * 32;

        // chunk idx -> slab ff = 30 - idx/9 (step computes z_ff), row block cc
        auto issue = [&](int idx) {
            int ff = 30 - idx / CPS, cc = idx - (30 - ff) * CPS;
            const float* base = W + ((size_t)ff * N + cc * CW) * N + c0;
            uint32_t dst = sbase + (uint32_t)(idx % RING) * (SLOT_FLOATS * 4);
            #pragma unroll
            for (int k = 0; k < 2; ++k) {
                int e = tid + k * 1024;          // e = row*8 + part (row<256, part<8)
                int row = e >> 3, part = e & 7;
                cpasync16(dst + (uint32_t)e * 16, base + (size_t)row * N + part * 4);
            }
            cpcommit();
        };

        int issued = 0;
        #pragma unroll
        for (int i = 0; i < DEPTH; ++i) issue(issued++);

        if (tid < 32) g_z[31 * N + c0 + tid] = 1.0f;
        teambar(g_cntB, 0);

        for (int f = FF - 2; f >= 0; --f) {
            for (int n = tid; n < N; n += NTHR)
                s_v[n] = g_keep[(f + 1) * N + n] * g_z[(f + 1) * N + n];

            float p = 0.f;
            int g0 = (30 - f) * CPS;
            #pragma unroll
            for (int c = 0; c < CPS; ++c) {
                if (issued < TOTAL) cpwait3(); else cpwait0();
                __syncthreads();
                if (issued < TOTAL) issue(issued++);

                const float* sw = s_slot + ((g0 + c) % RING) * SLOT_FLOATS;
                const float* vv = s_v + c * CW;
                #pragma unroll
                for (int j = 0; j < 8; ++j) {    // row r = warp + 32*j within chunk
                    int r = warp + j * 32;
                    p += sw[r * 32 + lane] * vv[r];
                }
            }
            // transpose into padded smem, one sync, warp-shuffle reduce
            __syncthreads();                     // all chunk consumption done (reuse s_red safely)
            s_red[lane * 33 + warp] = p;
            __syncthreads();
            float q = s_red[warp * 33 + lane];
            #pragma unroll
            for (int o = 16; o; o >>= 1)
                q += __shfl_xor_sync(0xffffffffu, q, o);
            if (lane == 0) g_z[f * N + c0 + warp] = 1.0f + q;
            if (f > 0) teambar(g_cntB, 31 - f);
        }
    }

    // ================= FUSED FINAL =================
    __threadfence();
    __syncthreads();
    if (tid == 0) atomicAdd(&g_cntAll, 1);
    if (cta == 0) {
        if (tid == 0) {
            volatile int* c = &g_cntAll;
            while (*c < NCTA) { }
            __threadfence();
        }
        __syncthreads();
        float t = (tid < TEAM) ? g_vsum[tid] : 0.f;
        if (tid < 128) {
            #pragma unroll
            for (int o = 16; o; o >>= 1) t += __shfl_xor_sync(0xffffffffu, t, o);
            if ((tid & 31) == 0) s_red[tid >> 5] = t;
        }
        __syncthreads();
        if (tid == 0) s_red[0] = s_red[0] + s_red[1] + s_red[2] + s_red[3];
        __syncthreads();
        float TOT = s_red[0];
        int cf = cand[3 * tid];
        int cn = cand[3 * tid + 1] * 64 + cand[3 * tid + 2];
        out[tid] = TOT - g_v[cf * N + cn] * g_z[cf * N + cn];
    }
}

extern "C" void kernel_launch(void* const* d_in, const int* in_sizes, int n_in,
                              void* d_out, int out_size) {
    const float* weights = (const float*)d_in[0];
    const float* biases  = (const float*)d_in[1];
    const int*   sel     = (const int*)d_in[2];
    const int*   cand    = (const int*)d_in[3];
    float*       out     = (float*)d_out;

    cudaFuncSetAttribute(solve_kernel, cudaFuncAttributeMaxDynamicSharedMemorySize, SMEM_BYTES);

    setup_kernel<<<1, NTHR>>>(sel);
    solve_kernel<<<NCTA, NTHR, SMEM_BYTES>>>(weights, biases, cand, out);
}